// round 2
// baseline (speedup 1.0000x reference)
#include <cuda_runtime.h>
#include <cuda_bf16.h>
#include <cstdint>

// RadiusGraph with PBC minimum-image wrap.
// out layout: [0 .. 3*N*N)  disp  [N,N,3] f32
//             [3*N*N .. 4*N*N) mask [N,N]  f32 (0/1)

#define R_CUT 5.0f
#define MAX_B 64
#define MAX_N 8192

__device__ float g_cell[MAX_B * 9];     // cell[b][r][c] row-major
__device__ float g_invT[MAX_B * 9];     // inv(cell[b]^T)[r][c] row-major
__device__ float g_tpos[MAX_N * 3];     // invT[batch[n]] . pos[n]

// One thread per batch: build inv(cell^T) in double precision.
__global__ void precompute_inv_kernel(const float* __restrict__ cell, int B) {
    int b = threadIdx.x;
    if (b >= B) return;
    double m[3][3];
#pragma unroll
    for (int r = 0; r < 3; r++)
#pragma unroll
        for (int c = 0; c < 3; c++)
            m[r][c] = (double)cell[b * 9 + r * 3 + c];

    // A = cell^T
    double a00 = m[0][0], a01 = m[1][0], a02 = m[2][0];
    double a10 = m[0][1], a11 = m[1][1], a12 = m[2][1];
    double a20 = m[0][2], a21 = m[1][2], a22 = m[2][2];

    double C00 =  a11 * a22 - a12 * a21;
    double C01 = -(a10 * a22 - a12 * a20);
    double C02 =  a10 * a21 - a11 * a20;
    double det = a00 * C00 + a01 * C01 + a02 * C02;
    double id  = 1.0 / det;

    double inv[3][3];
    inv[0][0] = C00 * id;
    inv[1][0] = C01 * id;
    inv[2][0] = C02 * id;
    inv[0][1] = (a02 * a21 - a01 * a22) * id;
    inv[1][1] = (a00 * a22 - a02 * a20) * id;
    inv[2][1] = -(a00 * a21 - a01 * a20) * id;
    inv[0][2] = (a01 * a12 - a02 * a11) * id;
    inv[1][2] = -(a00 * a12 - a02 * a10) * id;
    inv[2][2] = (a00 * a11 - a01 * a10) * id;

#pragma unroll
    for (int r = 0; r < 3; r++)
#pragma unroll
        for (int c = 0; c < 3; c++) {
            g_cell[b * 9 + r * 3 + c] = (float)m[r][c];
            g_invT[b * 9 + r * 3 + c] = (float)inv[r][c];
        }
}

// Per-atom fractional coordinates: tpos[n] = invT[batch[n]] . pos[n]
__global__ void precompute_tpos_kernel(const float* __restrict__ pos,
                                       const int* __restrict__ batch, int n) {
    int t = blockIdx.x * blockDim.x + threadIdx.x;
    if (t >= n) return;
    int b = batch[t];
    float x = pos[t * 3 + 0], y = pos[t * 3 + 1], z = pos[t * 3 + 2];
    const float* T = g_invT + b * 9;
    g_tpos[t * 3 + 0] = T[0] * x + T[1] * y + T[2] * z;
    g_tpos[t * 3 + 1] = T[3] * x + T[4] * y + T[5] * z;
    g_tpos[t * 3 + 2] = T[6] * x + T[7] * y + T[8] * z;
}

// 128 threads/block; each thread handles 4 consecutive j for a fixed row i.
// grid.x = N / 512, grid.y = N.
__global__ __launch_bounds__(128, 12) void radius_graph_kernel(
    const float* __restrict__ pos,
    const int*   __restrict__ batch,
    float* __restrict__ out,
    int n)
{
    const int i  = blockIdx.y;
    const int j0 = (blockIdx.x * blockDim.x + threadIdx.x) * 4;

    const int   bi  = __ldg(&batch[i]);
    const float pix = __ldg(&pos[i * 3 + 0]);
    const float piy = __ldg(&pos[i * 3 + 1]);
    const float piz = __ldg(&pos[i * 3 + 2]);
    const float tix = g_tpos[i * 3 + 0];
    const float tiy = g_tpos[i * 3 + 1];
    const float tiz = g_tpos[i * 3 + 2];

    float cm[9];
#pragma unroll
    for (int k = 0; k < 9; k++) cm[k] = g_cell[bi * 9 + k];

    // Load 4 positions (12 floats) as 3 float4 each.
    const float4* p4 = reinterpret_cast<const float4*>(pos + (size_t)j0 * 3);
    float4 q0 = p4[0], q1 = p4[1], q2 = p4[2];
    const float4* t4 = reinterpret_cast<const float4*>(g_tpos + (size_t)j0 * 3);
    float4 u0 = t4[0], u1 = t4[1], u2 = t4[2];

    float px[4] = {q0.x, q0.w, q1.z, q2.y};
    float py[4] = {q0.y, q1.x, q1.w, q2.z};
    float pz[4] = {q0.z, q1.y, q2.x, q2.w};
    float tx[4] = {u0.x, u0.w, u1.z, u2.y};
    float ty[4] = {u0.y, u1.x, u1.w, u2.z};
    float tz[4] = {u0.z, u1.y, u2.x, u2.w};

    int4 b4 = *reinterpret_cast<const int4*>(batch + j0);
    int  bj[4] = {b4.x, b4.y, b4.z, b4.w};

    float dx[4], dy[4], dz[4], mk[4];
#pragma unroll
    for (int k = 0; k < 4; k++) {
        float ddx = pix - px[k];
        float ddy = piy - py[k];
        float ddz = piz - pz[k];

        float s0 = rintf(tix - tx[k]);
        float s1 = rintf(tiy - ty[k]);
        float s2 = rintf(tiz - tz[k]);

        ddx -= cm[0] * s0 + cm[1] * s1 + cm[2] * s2;
        ddy -= cm[3] * s0 + cm[4] * s1 + cm[5] * s2;
        ddz -= cm[6] * s0 + cm[7] * s1 + cm[8] * s2;

        bool ok = (bi == bj[k]) && (i != (j0 + k)) &&
                  (sqrtf(ddx * ddx + ddy * ddy + ddz * ddz) < R_CUT);
        dx[k] = ok ? ddx : 0.0f;
        dy[k] = ok ? ddy : 0.0f;
        dz[k] = ok ? ddz : 0.0f;
        mk[k] = ok ? 1.0f : 0.0f;
    }

    float* od = out + (size_t)i * n * 3 + (size_t)j0 * 3;
    reinterpret_cast<float4*>(od)[0] = make_float4(dx[0], dy[0], dz[0], dx[1]);
    reinterpret_cast<float4*>(od)[1] = make_float4(dy[1], dz[1], dx[2], dy[2]);
    reinterpret_cast<float4*>(od)[2] = make_float4(dz[2], dx[3], dy[3], dz[3]);

    float* om = out + (size_t)3 * n * n + (size_t)i * n + j0;
    reinterpret_cast<float4*>(om)[0] = make_float4(mk[0], mk[1], mk[2], mk[3]);
}

extern "C" void kernel_launch(void* const* d_in, const int* in_sizes, int n_in,
                              void* d_out, int out_size) {
    const float* pos   = (const float*)d_in[0];
    const float* cell  = (const float*)d_in[1];
    const int*   batch = (const int*)d_in[2];
    float* out = (float*)d_out;

    const int n = in_sizes[0] / 3;      // 4096
    const int B = in_sizes[1] / 9;      // 8

    precompute_inv_kernel<<<1, 32>>>(cell, B);
    precompute_tpos_kernel<<<(n + 255) / 256, 256>>>(pos, batch, n);

    dim3 block(128);
    dim3 grid(n / 512, n);
    radius_graph_kernel<<<grid, block>>>(pos, batch, out, n);
}

// round 3
// speedup vs baseline: 1.1688x; 1.1688x over previous
#include <cuda_runtime.h>
#include <cuda_bf16.h>
#include <cstdint>

// RadiusGraph with PBC minimum-image wrap. Single self-contained kernel.
// out layout: [0 .. 3*N*N)  disp  [N,N,3] f32
//             [3*N*N .. 4*N*N) mask [N,N]  f32 (0/1)

#define R2_CUT 25.0f   // R = 5.0
#define MAX_B  16
#define TI     8       // i-rows per block

__global__ __launch_bounds__(128, 8) void radius_graph_kernel(
    const float* __restrict__ pos,
    const float* __restrict__ cell,
    const int*   __restrict__ batch,
    float* __restrict__ out,
    int n, int B)
{
    __shared__ float s_invT[MAX_B][9];  // inv(cell^T) row-major
    __shared__ float s_cell[MAX_B][9];  // cell row-major
    __shared__ float s_ip[TI][8];       // pix,piy,piz,tix,tiy,tiz,bi

    const int tid = threadIdx.x;

    // Phase 1: per-batch inverse of cell^T (float; feeds only rint(), safe).
    if (tid < B) {
        float m[9];
#pragma unroll
        for (int k = 0; k < 9; k++) m[k] = cell[tid * 9 + k];
        // A = cell^T
        float a00 = m[0], a01 = m[3], a02 = m[6];
        float a10 = m[1], a11 = m[4], a12 = m[7];
        float a20 = m[2], a21 = m[5], a22 = m[8];
        float C00 =  a11 * a22 - a12 * a21;
        float C01 = -(a10 * a22 - a12 * a20);
        float C02 =  a10 * a21 - a11 * a20;
        float det = a00 * C00 + a01 * C01 + a02 * C02;
        float id  = 1.0f / det;
        s_invT[tid][0] = C00 * id;
        s_invT[tid][3] = C01 * id;
        s_invT[tid][6] = C02 * id;
        s_invT[tid][1] = (a02 * a21 - a01 * a22) * id;
        s_invT[tid][4] = (a00 * a22 - a02 * a20) * id;
        s_invT[tid][7] = -(a00 * a21 - a01 * a20) * id;
        s_invT[tid][2] = (a01 * a12 - a02 * a11) * id;
        s_invT[tid][5] = -(a00 * a12 - a02 * a10) * id;
        s_invT[tid][8] = (a00 * a11 - a01 * a10) * id;
#pragma unroll
        for (int k = 0; k < 9; k++) s_cell[tid][k] = m[k];
    }
    __syncthreads();

    // Phase 2a: i-row data (8 threads).
    const int i0 = blockIdx.y * TI;
    if (tid < TI) {
        int i  = i0 + tid;
        int bi = batch[i];
        float x = pos[i * 3 + 0], y = pos[i * 3 + 1], z = pos[i * 3 + 2];
        const float* T = s_invT[bi];
        s_ip[tid][0] = x;
        s_ip[tid][1] = y;
        s_ip[tid][2] = z;
        s_ip[tid][3] = T[0] * x + T[1] * y + T[2] * z;
        s_ip[tid][4] = T[3] * x + T[4] * y + T[5] * z;
        s_ip[tid][5] = T[6] * x + T[7] * y + T[8] * z;
        s_ip[tid][6] = __int_as_float(bi);
    }

    // Phase 2b: j-column data, 4 consecutive j per thread (registers).
    const int j0 = (blockIdx.x * blockDim.x + tid) * 4;
    const float4* p4 = reinterpret_cast<const float4*>(pos + (size_t)j0 * 3);
    float4 q0 = p4[0], q1 = p4[1], q2 = p4[2];
    float px[4] = {q0.x, q0.w, q1.z, q2.y};
    float py[4] = {q0.y, q1.x, q1.w, q2.z};
    float pz[4] = {q0.z, q1.y, q2.x, q2.w};
    int4 b4 = *reinterpret_cast<const int4*>(batch + j0);
    int  bj[4] = {b4.x, b4.y, b4.z, b4.w};
    float tx[4], ty[4], tz[4];
#pragma unroll
    for (int k = 0; k < 4; k++) {
        const float* T = s_invT[bj[k]];
        tx[k] = T[0] * px[k] + T[1] * py[k] + T[2] * pz[k];
        ty[k] = T[3] * px[k] + T[4] * py[k] + T[5] * pz[k];
        tz[k] = T[6] * px[k] + T[7] * py[k] + T[8] * pz[k];
    }
    __syncthreads();

    // Main loop: 8 i-rows × 4 j-cols per thread.
#pragma unroll
    for (int ii = 0; ii < TI; ii++) {
        const int i = i0 + ii;
        const float pix = s_ip[ii][0], piy = s_ip[ii][1], piz = s_ip[ii][2];
        const float tix = s_ip[ii][3], tiy = s_ip[ii][4], tiz = s_ip[ii][5];
        const int   bi  = __float_as_int(s_ip[ii][6]);
        const float* cm = s_cell[bi];

        float dx[4], dy[4], dz[4], mk[4];
#pragma unroll
        for (int k = 0; k < 4; k++) {
            float ddx = pix - px[k];
            float ddy = piy - py[k];
            float ddz = piz - pz[k];
            float s0 = rintf(tix - tx[k]);
            float s1 = rintf(tiy - ty[k]);
            float s2 = rintf(tiz - tz[k]);
            ddx -= cm[0] * s0 + cm[1] * s1 + cm[2] * s2;
            ddy -= cm[3] * s0 + cm[4] * s1 + cm[5] * s2;
            ddz -= cm[6] * s0 + cm[7] * s1 + cm[8] * s2;
            bool ok = (bi == bj[k]) && (i != (j0 + k)) &&
                      (ddx * ddx + ddy * ddy + ddz * ddz < R2_CUT);
            dx[k] = ok ? ddx : 0.0f;
            dy[k] = ok ? ddy : 0.0f;
            dz[k] = ok ? ddz : 0.0f;
            mk[k] = ok ? 1.0f : 0.0f;
        }

        float* od = out + ((size_t)i * n + j0) * 3;
        reinterpret_cast<float4*>(od)[0] = make_float4(dx[0], dy[0], dz[0], dx[1]);
        reinterpret_cast<float4*>(od)[1] = make_float4(dy[1], dz[1], dx[2], dy[2]);
        reinterpret_cast<float4*>(od)[2] = make_float4(dz[2], dx[3], dy[3], dz[3]);

        float* om = out + (size_t)3 * n * n + (size_t)i * n + j0;
        reinterpret_cast<float4*>(om)[0] = make_float4(mk[0], mk[1], mk[2], mk[3]);
    }
}

extern "C" void kernel_launch(void* const* d_in, const int* in_sizes, int n_in,
                              void* d_out, int out_size) {
    const float* pos   = (const float*)d_in[0];
    const float* cell  = (const float*)d_in[1];
    const int*   batch = (const int*)d_in[2];
    float* out = (float*)d_out;

    const int n = in_sizes[0] / 3;      // 4096
    const int B = in_sizes[1] / 9;      // 8

    dim3 block(128);
    dim3 grid(n / (128 * 4), n / TI);   // (8, 512)
    radius_graph_kernel<<<grid, block>>>(pos, cell, batch, out, n, B);
}

// round 4
// speedup vs baseline: 1.6971x; 1.4521x over previous
#include <cuda_runtime.h>
#include <cuda_bf16.h>
#include <cstdint>

// RadiusGraph with PBC minimum-image wrap. Compute tile -> SMEM -> TMA bulk store.
// out layout: [0 .. 3*N*N)  disp  [N,N,3] f32
//             [3*N*N .. 4*N*N) mask [N,N]  f32 (0/1)

#define R2_CUT 25.0f   // R = 5.0
#define MAX_B  16
#define TI     4                    // i-rows per block
#define JT     512                  // j-columns per block
#define THREADS 256
#define JPT    (JT / THREADS)       // 2 j's per thread (strided by THREADS)

#define DISP_F (TI * JT * 3)
#define MASK_F (TI * JT)
#define SMEM_BYTES ((DISP_F + MASK_F) * 4)

__device__ __forceinline__ uint32_t smem_u32(const void* p) {
    return (uint32_t)__cvta_generic_to_shared(p);
}

__global__ __launch_bounds__(THREADS) void radius_graph_kernel(
    const float* __restrict__ pos,
    const float* __restrict__ cell,
    const int*   __restrict__ batch,
    float* __restrict__ out,
    int n, int B)
{
    extern __shared__ float s_tile[];          // [DISP_F] disp + [MASK_F] mask
    float* s_disp = s_tile;
    float* s_mask = s_tile + DISP_F;

    __shared__ float s_invT[MAX_B][9];
    __shared__ float s_cell[MAX_B][9];
    __shared__ float s_ip[TI][8];              // pix,piy,piz,tix,tiy,tiz,bi

    const int tid = threadIdx.x;

    // Phase 1: per-batch inverse of cell^T (float; feeds only rint(), safe).
    if (tid < B) {
        float m[9];
#pragma unroll
        for (int k = 0; k < 9; k++) m[k] = cell[tid * 9 + k];
        float a00 = m[0], a01 = m[3], a02 = m[6];
        float a10 = m[1], a11 = m[4], a12 = m[7];
        float a20 = m[2], a21 = m[5], a22 = m[8];
        float C00 =  a11 * a22 - a12 * a21;
        float C01 = -(a10 * a22 - a12 * a20);
        float C02 =  a10 * a21 - a11 * a20;
        float det = a00 * C00 + a01 * C01 + a02 * C02;
        float id  = 1.0f / det;
        s_invT[tid][0] = C00 * id;
        s_invT[tid][3] = C01 * id;
        s_invT[tid][6] = C02 * id;
        s_invT[tid][1] = (a02 * a21 - a01 * a22) * id;
        s_invT[tid][4] = (a00 * a22 - a02 * a20) * id;
        s_invT[tid][7] = -(a00 * a21 - a01 * a20) * id;
        s_invT[tid][2] = (a01 * a12 - a02 * a11) * id;
        s_invT[tid][5] = -(a00 * a12 - a02 * a10) * id;
        s_invT[tid][8] = (a00 * a11 - a01 * a10) * id;
#pragma unroll
        for (int k = 0; k < 9; k++) s_cell[tid][k] = m[k];
    }
    __syncthreads();

    // Phase 2a: i-row data.
    const int i0 = blockIdx.y * TI;
    if (tid < TI) {
        int i  = i0 + tid;
        int bi = batch[i];
        float x = pos[i * 3 + 0], y = pos[i * 3 + 1], z = pos[i * 3 + 2];
        const float* T = s_invT[bi];
        s_ip[tid][0] = x;
        s_ip[tid][1] = y;
        s_ip[tid][2] = z;
        s_ip[tid][3] = T[0] * x + T[1] * y + T[2] * z;
        s_ip[tid][4] = T[3] * x + T[4] * y + T[5] * z;
        s_ip[tid][5] = T[6] * x + T[7] * y + T[8] * z;
        s_ip[tid][6] = __int_as_float(bi);
    }

    // Phase 2b: j-column data, JPT strided j's per thread (jl = tid + m*THREADS).
    const int j0 = blockIdx.x * JT;
    float px[JPT], py[JPT], pz[JPT], tx[JPT], ty[JPT], tz[JPT];
    int   bj[JPT];
#pragma unroll
    for (int m = 0; m < JPT; m++) {
        int j = j0 + tid + m * THREADS;
        px[m] = pos[j * 3 + 0];
        py[m] = pos[j * 3 + 1];
        pz[m] = pos[j * 3 + 2];
        bj[m] = batch[j];
    }
    __syncthreads();   // s_invT / s_ip ready
#pragma unroll
    for (int m = 0; m < JPT; m++) {
        const float* T = s_invT[bj[m]];
        tx[m] = T[0] * px[m] + T[1] * py[m] + T[2] * pz[m];
        ty[m] = T[3] * px[m] + T[4] * py[m] + T[5] * pz[m];
        tz[m] = T[6] * px[m] + T[7] * py[m] + T[8] * pz[m];
    }

    // Main loop: TI rows x JPT strided cols; write results to SMEM tile.
#pragma unroll
    for (int ii = 0; ii < TI; ii++) {
        const int i = i0 + ii;
        const float pix = s_ip[ii][0], piy = s_ip[ii][1], piz = s_ip[ii][2];
        const float tix = s_ip[ii][3], tiy = s_ip[ii][4], tiz = s_ip[ii][5];
        const int   bi  = __float_as_int(s_ip[ii][6]);
        const float* cm = s_cell[bi];

#pragma unroll
        for (int m = 0; m < JPT; m++) {
            const int jl = tid + m * THREADS;
            float ddx = pix - px[m];
            float ddy = piy - py[m];
            float ddz = piz - pz[m];
            float s0 = rintf(tix - tx[m]);
            float s1 = rintf(tiy - ty[m]);
            float s2 = rintf(tiz - tz[m]);
            ddx -= cm[0] * s0 + cm[1] * s1 + cm[2] * s2;
            ddy -= cm[3] * s0 + cm[4] * s1 + cm[5] * s2;
            ddz -= cm[6] * s0 + cm[7] * s1 + cm[8] * s2;
            bool ok = (bi == bj[m]) && (i != (j0 + jl)) &&
                      (ddx * ddx + ddy * ddy + ddz * ddz < R2_CUT);

            float* d = s_disp + (ii * JT + jl) * 3;   // byte addr stride 12*lane: conflict-free
            d[0] = ok ? ddx : 0.0f;
            d[1] = ok ? ddy : 0.0f;
            d[2] = ok ? ddz : 0.0f;
            s_mask[ii * JT + jl] = ok ? 1.0f : 0.0f;
        }
    }

    __syncthreads();   // all STS visible block-wide

    // Phase 3: drain the tile via TMA bulk stores (bypasses L1 STG path).
    if (tid == 0) {
        asm volatile("fence.proxy.async.shared::cta;" ::: "memory");
        uint32_t sd = smem_u32(s_disp);
        uint32_t sm = smem_u32(s_mask);
#pragma unroll
        for (int ii = 0; ii < TI; ii++) {
            const float* gd = out + ((size_t)(i0 + ii) * n + j0) * 3;
            asm volatile(
                "cp.async.bulk.global.shared::cta.bulk_group [%0], [%1], %2;"
                :: "l"(gd), "r"(sd + ii * JT * 3 * 4), "r"(JT * 3 * 4)
                : "memory");
        }
#pragma unroll
        for (int ii = 0; ii < TI; ii++) {
            const float* gm = out + (size_t)3 * n * n + (size_t)(i0 + ii) * n + j0;
            asm volatile(
                "cp.async.bulk.global.shared::cta.bulk_group [%0], [%1], %2;"
                :: "l"(gm), "r"(sm + ii * JT * 4), "r"(JT * 4)
                : "memory");
        }
        asm volatile("cp.async.bulk.commit_group;" ::: "memory");
        asm volatile("cp.async.bulk.wait_group 0;" ::: "memory");
    }
}

extern "C" void kernel_launch(void* const* d_in, const int* in_sizes, int n_in,
                              void* d_out, int out_size) {
    const float* pos   = (const float*)d_in[0];
    const float* cell  = (const float*)d_in[1];
    const int*   batch = (const int*)d_in[2];
    float* out = (float*)d_out;

    const int n = in_sizes[0] / 3;      // 4096
    const int B = in_sizes[1] / 9;      // 8

    static bool attr_set = false;
    if (!attr_set) {
        cudaFuncSetAttribute(radius_graph_kernel,
                             cudaFuncAttributeMaxDynamicSharedMemorySize,
                             SMEM_BYTES);
        attr_set = true;
    }

    dim3 block(THREADS);
    dim3 grid(n / JT, n / TI);          // (8, 1024)
    radius_graph_kernel<<<grid, block, SMEM_BYTES>>>(pos, cell, batch, out, n, B);
}